// round 14
// baseline (speedup 1.0000x reference)
#include <cuda_runtime.h>
#include <cuda_bf16.h>
#include <math.h>
#include <stdint.h>

// Problem constants
#define T_TOK 2048
#define H_DIM 1024
#define I_DIM 512
#define NE    16
#define TK    4
#define NPAIR (T_TOK * TK)   // 8192

// ---------------- scratch (device globals; no allocation) ----------------
__device__ int   g_offsets[NE + 1];
__device__ int   g_ids[NPAIR];
__device__ float g_wt[NPAIR];
__device__ int   g_slot[NPAIR];
__device__ int   g_hcnt[NPAIR];          // pass1 row-completion counters
__device__ int   g_ocnt[T_TOK * 16];     // pass2 (token, ntile) counters

// int8 two-level quantized pass1 inputs + per-row scales
__device__ __align__(16) signed char g_x1[T_TOK * H_DIM];
__device__ __align__(16) signed char g_x2[T_TOK * H_DIM];
__device__ __align__(16) signed char g_u1[NE * I_DIM * H_DIM];
__device__ __align__(16) signed char g_u2[NE * I_DIM * H_DIM];
__device__ __align__(16) signed char g_g1[NE * I_DIM * H_DIM];
__device__ __align__(16) signed char g_g2[NE * I_DIM * H_DIM];
__device__ float g_sx[T_TOK];
__device__ float g_su[NE * I_DIM];
__device__ float g_sg[NE * I_DIM];

// pass2 operands
__device__ __align__(16) float g_h[(size_t)NPAIR * I_DIM];
__device__ __align__(16) signed char g_h1[(size_t)NPAIR * I_DIM];
__device__ __align__(16) signed char g_h2[(size_t)NPAIR * I_DIM];
__device__ float g_sh[NPAIR];
__device__ __align__(16) signed char g_wd1[NE * H_DIM * I_DIM];
__device__ __align__(16) signed char g_wd2[NE * H_DIM * I_DIM];
__device__ float g_swd[NE * H_DIM];

__device__ __align__(16) float g_part[(size_t)NPAIR * H_DIM];   // 32 MB

// ---------------- helpers ----------------
__device__ __forceinline__ uint32_t smem_u32(const void* p) {
    uint32_t a;
    asm("{ .reg .u64 t; cvta.to.shared.u64 t, %1; cvt.u32.u64 %0, t; }" : "=r"(a) : "l"(p));
    return a;
}
__device__ __forceinline__ void cp_async16(uint32_t dst, const void* src) {
    asm volatile("cp.async.cg.shared.global [%0], [%1], 16;" :: "r"(dst), "l"(src));
}
__device__ __forceinline__ void ldmx4(uint32_t r[4], uint32_t addr) {
    asm volatile("ldmatrix.sync.aligned.m8n8.x4.shared.b16 {%0,%1,%2,%3}, [%4];"
                 : "=r"(r[0]), "=r"(r[1]), "=r"(r[2]), "=r"(r[3]) : "r"(addr));
}
__device__ __forceinline__ void imma16832(int d[4], const uint32_t a[4], uint32_t b0, uint32_t b1) {
    asm("mma.sync.aligned.m16n8k32.row.col.s32.s8.s8.s32 "
        "{%0,%1,%2,%3}, {%4,%5,%6,%7}, {%8,%9}, {%0,%1,%2,%3};"
        : "+r"(d[0]), "+r"(d[1]), "+r"(d[2]), "+r"(d[3])
        : "r"(a[0]), "r"(a[1]), "r"(a[2]), "r"(a[3]), "r"(b0), "r"(b1));
}
#define SWZ(o) ((o) ^ (((o) >> 3) & 0x70))

// ============================================================================
// prep kernel: zero completion counters; block 0 = routing; blocks
// [1..NB_CONV1] = conv_int8 rows; remaining = conv_wd8 rows.
// ============================================================================
#define CONV8_ROWS (T_TOK + 2 * NE * I_DIM)
#define NB_CONV1   ((CONV8_ROWS + 3) / 4)
#define NB_WD      ((NE * H_DIM + 7) / 8)
#define NB_PREP    (1 + NB_CONV1 + NB_WD)

__global__ void __launch_bounds__(512) prep_kernel(const float* __restrict__ logits,
                                                   const float* __restrict__ x,
                                                   const float* __restrict__ wu,
                                                   const float* __restrict__ wg,
                                                   const float* __restrict__ wd) {
    int bid = blockIdx.x;
    int tid = threadIdx.x;

    // zero completion counters for this launch (graph-replay safe)
    {
        int z = bid * 512 + tid;
        if (z < NPAIR) g_hcnt[z] = 0;
        if (z < T_TOK * 16) g_ocnt[z] = 0;
    }

    if (bid == 0) {
        __shared__ int s_cnt[NE], s_cur[NE], s_off[NE + 1];
        if (tid < NE) { s_cnt[tid] = 0; s_cur[tid] = 0; }
        __syncthreads();
        for (int t = tid; t < T_TOK; t += 512) {
            float l[NE];
#pragma unroll
            for (int e = 0; e < NE; e++) l[e] = logits[t * NE + e];
            int ids[TK]; float vals[TK];
            unsigned mask = 0;
#pragma unroll
            for (int k = 0; k < TK; k++) {
                float best = -1e30f; int bi = 0;
#pragma unroll
                for (int e = 0; e < NE; e++)
                    if (!((mask >> e) & 1u) && l[e] > best) { best = l[e]; bi = e; }
                ids[k] = bi; vals[k] = best; mask |= (1u << bi);
            }
            float m = vals[0];
            float w[TK]; float s = 0.f;
#pragma unroll
            for (int k = 0; k < TK; k++) { w[k] = expf(vals[k] - m); s += w[k]; }
            float inv = 1.f / s;
#pragma unroll
            for (int k = 0; k < TK; k++) {
                g_ids[t * TK + k] = ids[k];
                g_wt[t * TK + k]  = w[k] * inv;
                atomicAdd(&s_cnt[ids[k]], 1);
            }
        }
        __syncthreads();
        if (tid == 0) {
            int acc = 0;
            s_off[0] = 0; g_offsets[0] = 0;
#pragma unroll
            for (int e = 0; e < NE; e++) {
                acc += s_cnt[e];
                s_off[e + 1] = acc;
                g_offsets[e + 1] = acc;
            }
        }
        __syncthreads();
        for (int t = tid; t < T_TOK; t += 512) {
#pragma unroll
            for (int k = 0; k < TK; k++) {
                int e = g_ids[t * TK + k];
                int pos = s_off[e] + atomicAdd(&s_cur[e], 1);
                g_slot[pos] = t * TK + k;
            }
        }
        return;
    }

    if (bid <= NB_CONV1) {
        int grp = tid >> 7;
        int lt  = tid & 127;
        int r = (bid - 1) * 4 + grp;
        bool active = r < CONV8_ROWS;

        const float* src = x; signed char* q1 = g_x1; signed char* q2 = g_x2; float* sc = g_sx; int row = 0;
        if (active) {
            if (r < T_TOK)                 { src = x;  q1 = g_x1; q2 = g_x2; sc = g_sx; row = r; }
            else if (r < T_TOK + NE*I_DIM) { src = wu; q1 = g_u1; q2 = g_u2; sc = g_su; row = r - T_TOK; }
            else                           { src = wg; q1 = g_g1; q2 = g_g2; sc = g_sg; row = r - T_TOK - NE*I_DIM; }
        }

        float v[8] = {0, 0, 0, 0, 0, 0, 0, 0};
        if (active) {
            const float4* p4 = (const float4*)(src + (size_t)row * H_DIM + lt * 8);
            float4 a = p4[0], b = p4[1];
            v[0] = a.x; v[1] = a.y; v[2] = a.z; v[3] = a.w;
            v[4] = b.x; v[5] = b.y; v[6] = b.z; v[7] = b.w;
        }
        float m = 0.f;
#pragma unroll
        for (int j = 0; j < 8; j++) m = fmaxf(m, fabsf(v[j]));
#pragma unroll
        for (int o = 16; o; o >>= 1) m = fmaxf(m, __shfl_xor_sync(0xFFFFFFFFu, m, o));
        __shared__ float sm1[16];
        __shared__ float s_inv1[4];
        if ((lt & 31) == 0) sm1[grp * 4 + (lt >> 5)] = m;
        __syncthreads();
        if (lt == 0) {
            float mm = fmaxf(fmaxf(sm1[grp * 4], sm1[grp * 4 + 1]),
                             fmaxf(sm1[grp * 4 + 2], sm1[grp * 4 + 3]));
            if (active) sc[row] = mm * (1.f / 127.f);
            s_inv1[grp] = (mm > 0.f) ? (127.f / mm) : 0.f;
        }
        __syncthreads();
        if (!active) return;
        float inv = s_inv1[grp];
        unsigned long long u1 = 0, u2 = 0;
#pragma unroll
        for (int j = 0; j < 8; j++) {
            float t  = v[j] * inv;
            float t1 = rintf(t);
            int c1 = (int)t1;
            int c2 = (int)rintf((t - t1) * 128.f);
            u1 |= ((unsigned long long)(unsigned char)(signed char)c1) << (8 * j);
            u2 |= ((unsigned long long)(unsigned char)(signed char)c2) << (8 * j);
        }
        size_t o = (size_t)row * H_DIM + lt * 8;
        *(unsigned long long*)(q1 + o) = u1;
        *(unsigned long long*)(q2 + o) = u2;
        return;
    }

    {
        int grp = tid >> 6;
        int lt  = tid & 63;
        int row = (bid - 1 - NB_CONV1) * 8 + grp;
        bool active = row < NE * H_DIM;

        float v[8] = {0, 0, 0, 0, 0, 0, 0, 0};
        if (active) {
            const float4* p4 = (const float4*)(wd + (size_t)row * I_DIM + lt * 8);
            float4 a = p4[0], b = p4[1];
            v[0] = a.x; v[1] = a.y; v[2] = a.z; v[3] = a.w;
            v[4] = b.x; v[5] = b.y; v[6] = b.z; v[7] = b.w;
        }
        float m = 0.f;
#pragma unroll
        for (int j = 0; j < 8; j++) m = fmaxf(m, fabsf(v[j]));
#pragma unroll
        for (int o = 16; o; o >>= 1) m = fmaxf(m, __shfl_xor_sync(0xFFFFFFFFu, m, o));
        __shared__ float sm2[16];
        __shared__ float s_inv2[8];
        if ((lt & 31) == 0) sm2[grp * 2 + (lt >> 5)] = m;
        __syncthreads();
        if (lt == 0) {
            float mm = fmaxf(sm2[grp * 2], sm2[grp * 2 + 1]);
            if (active) g_swd[row] = mm * (1.f / 127.f);
            s_inv2[grp] = (mm > 0.f) ? (127.f / mm) : 0.f;
        }
        __syncthreads();
        if (!active) return;
        float inv = s_inv2[grp];
        unsigned long long u1 = 0, u2 = 0;
#pragma unroll
        for (int j = 0; j < 8; j++) {
            float t  = v[j] * inv;
            float t1 = rintf(t);
            int c1 = (int)t1;
            int c2 = (int)rintf((t - t1) * 128.f);
            u1 |= ((unsigned long long)(unsigned char)(signed char)c1) << (8 * j);
            u2 |= ((unsigned long long)(unsigned char)(signed char)c2) << (8 * j);
        }
        size_t o = (size_t)row * I_DIM + lt * 8;
        *(unsigned long long*)(g_wd1 + o) = u1;
        *(unsigned long long*)(g_wd2 + o) = u2;
    }
}

// ============================================================================
// pass1: grouped int8 IMMA GEMM, CTA 64x64, K=1024, fused up+gate,
// two-level int8 (3-term). Fold: last of 8 n-tile CTAs quantizes each h row.
// ============================================================================
#define P1_TILE  8192
#define P1_STAGE (6 * P1_TILE)                  // 48KB
#define P1_SMEM  (2048 + 2 * P1_STAGE)          // 100352 -> 2 CTAs/SM
#define P1_NC    8

__global__ void __launch_bounds__(256, 2) pass1_mma() {
    int e     = blockIdx.z;
    int mBase = g_offsets[e];
    int mEnd  = g_offsets[e + 1];
    int m0    = mBase + blockIdx.y * 64;
    if (m0 >= mEnd) return;
    int n0 = blockIdx.x * 64;

    extern __shared__ char smem[];
    int*   s_tok = (int*)smem;
    float* s_wt  = (float*)(smem + 256);
    float* s_sa  = (float*)(smem + 512);
    float* s_su  = (float*)(smem + 768);
    float* s_sg  = (float*)(smem + 1024);
    uint32_t tb  = smem_u32(smem + 2048);

    int tid = threadIdx.x, wid = tid >> 5, lane = tid & 31;
    for (int r = tid; r < 64; r += 256) {
        int gm = m0 + r;
        int slot = (gm < mEnd) ? g_slot[gm] : g_slot[mBase];
        int tok = slot >> 2;
        s_tok[r] = tok;
        s_wt[r]  = g_wt[slot];
        s_sa[r]  = g_sx[tok];
        s_su[r]  = g_su[e * I_DIM + n0 + r];
        s_sg[r]  = g_sg[e * I_DIM + n0 + r];
    }
    __syncthreads();

    int lrow = tid >> 2;
    int qp   = tid & 3;
    uint32_t rbase = (uint32_t)lrow * 128;
    uint32_t cswz  = (rbase >> 3) & 0x70;
    uint32_t d0 = rbase + (((uint32_t)(qp * 32)) ^ cswz);
    uint32_t d1 = rbase + (((uint32_t)(qp * 32 + 16)) ^ cswz);
    size_t aoff = (size_t)s_tok[lrow] * H_DIM + qp * 32;
    size_t boff = ((size_t)e * I_DIM + n0 + lrow) * H_DIM + qp * 32;
    const signed char* sA1 = g_x1 + aoff;
    const signed char* sA2 = g_x2 + aoff;
    const signed char* sU1 = g_u1 + boff;
    const signed char* sU2 = g_u2 + boff;
    const signed char* sG1 = g_g1 + boff;
    const signed char* sG2 = g_g2 + boff;

    int dU1[2][2][4], dU2[2][2][4], dG1[2][2][4], dG2[2][2][4];
#pragma unroll
    for (int a = 0; a < 2; a++)
#pragma unroll
        for (int b = 0; b < 2; b++)
#pragma unroll
            for (int c = 0; c < 4; c++) {
                dU1[a][b][c] = 0; dU2[a][b][c] = 0;
                dG1[a][b][c] = 0; dG2[a][b][c] = 0;
            }

    int wm = (wid >> 2) * 32;
    int wn = (wid & 3) * 16;
    int lgrp = lane >> 3, lr = lane & 7;
    int rowA = wm + (lgrp & 1) * 8 + lr;
    int rowB = wn + (lgrp >> 1) * 8 + lr;
    int colA = (lgrp >> 1) * 16;
    int colB = (lgrp & 1) * 16;

    {
        uint32_t sb_ = tb;
        cp_async16(sb_ + d0, sA1);                   cp_async16(sb_ + d1, sA1 + 16);
        cp_async16(sb_ + P1_TILE + d0, sA2);         cp_async16(sb_ + P1_TILE + d1, sA2 + 16);
        cp_async16(sb_ + 2 * P1_TILE + d0, sU1);     cp_async16(sb_ + 2 * P1_TILE + d1, sU1 + 16);
        cp_async16(sb_ + 3 * P1_TILE + d0, sU2);     cp_async16(sb_ + 3 * P1_TILE + d1, sU2 + 16);
        cp_async16(sb_ + 4 * P1_TILE + d0, sG1);     cp_async16(sb_ + 4 * P1_TILE + d1, sG1 + 16);
        cp_async16(sb_ + 5 * P1_TILE + d0, sG2);     cp_async16(sb_ + 5 * P1_TILE + d1, sG2 + 16);
        asm volatile("cp.async.commit_group;" ::: "memory");
    }

    for (int c = 0; c < P1_NC; c++) {
        if (c + 1 < P1_NC) {
            int k0 = (c + 1) * 128;
            uint32_t sb_ = tb + ((c + 1) & 1) * P1_STAGE;
            cp_async16(sb_ + d0, sA1 + k0);                cp_async16(sb_ + d1, sA1 + k0 + 16);
            cp_async16(sb_ + P1_TILE + d0, sA2 + k0);      cp_async16(sb_ + P1_TILE + d1, sA2 + k0 + 16);
            cp_async16(sb_ + 2 * P1_TILE + d0, sU1 + k0);  cp_async16(sb_ + 2 * P1_TILE + d1, sU1 + k0 + 16);
            cp_async16(sb_ + 3 * P1_TILE + d0, sU2 + k0);  cp_async16(sb_ + 3 * P1_TILE + d1, sU2 + k0 + 16);
            cp_async16(sb_ + 4 * P1_TILE + d0, sG1 + k0);  cp_async16(sb_ + 4 * P1_TILE + d1, sG1 + k0 + 16);
            cp_async16(sb_ + 5 * P1_TILE + d0, sG2 + k0);  cp_async16(sb_ + 5 * P1_TILE + d1, sG2 + k0 + 16);
            asm volatile("cp.async.commit_group;" ::: "memory");
            asm volatile("cp.async.wait_group 1;" ::: "memory");
        } else {
            asm volatile("cp.async.wait_group 0;" ::: "memory");
        }
        __syncthreads();

        uint32_t st = tb + (c & 1) * P1_STAGE;
        uint32_t aQ1 = st, aQ2 = st + P1_TILE;
        uint32_t bU1 = st + 2 * P1_TILE, bU2 = st + 3 * P1_TILE;
        uint32_t bG1 = st + 4 * P1_TILE, bG2 = st + 5 * P1_TILE;

#pragma unroll
        for (int s = 0; s < 4; s++) {
            int kaB = s * 32 + colA;
            int kbB = s * 32 + colB;
            uint32_t A1f[2][4], A2f[2][4];
            ldmx4(A1f[0], aQ1 + SWZ(rowA * 128 + kaB));
            ldmx4(A1f[1], aQ1 + SWZ((rowA + 16) * 128 + kaB));
            ldmx4(A2f[0], aQ2 + SWZ(rowA * 128 + kaB));
            ldmx4(A2f[1], aQ2 + SWZ((rowA + 16) * 128 + kaB));
            uint32_t U1f[4], U2f[4], G1f[4], G2f[4];
            {
                uint32_t off = SWZ(rowB * 128 + kbB);
                ldmx4(U1f, bU1 + off);
                ldmx4(U2f, bU2 + off);
                ldmx4(G1f, bG1 + off);
                ldmx4(G2f, bG2 + off);
            }
#pragma unroll
            for (int mi = 0; mi < 2; mi++)
#pragma unroll
                for (int nf = 0; nf < 2; nf++) {
                    imma16832(dU1[mi][nf], A1f[mi], U1f[nf * 2], U1f[nf * 2 + 1]);
                    imma16832(dG1[mi][nf], A1f[mi], G1f[nf * 2], G1f[nf * 2 + 1]);
                }
#pragma unroll
            for (int mi = 0; mi < 2; mi++)
#pragma unroll
                for (int nf = 0; nf < 2; nf++) {
                    imma16832(dU2[mi][nf], A1f[mi], U2f[nf * 2], U2f[nf * 2 + 1]);
                    imma16832(dG2[mi][nf], A1f[mi], G2f[nf * 2], G2f[nf * 2 + 1]);
                }
#pragma unroll
            for (int mi = 0; mi < 2; mi++)
#pragma unroll
                for (int nf = 0; nf < 2; nf++) {
                    imma16832(dU2[mi][nf], A2f[mi], U1f[nf * 2], U1f[nf * 2 + 1]);
                    imma16832(dG2[mi][nf], A2f[mi], G1f[nf * 2], G1f[nf * 2 + 1]);
                }
        }
        __syncthreads();
    }

    // ---- epilogue: dequant, h = w * silu(w*g) * (w*u), store fp32 ----
    int r4 = lane >> 2, c2 = (lane & 3) * 2;
#pragma unroll
    for (int mi = 0; mi < 2; mi++) {
#pragma unroll
        for (int half = 0; half < 2; half++) {
            int row = wm + mi * 16 + half * 8 + r4;
            int gm  = m0 + row;
            if (gm >= mEnd) continue;
            float w  = s_wt[row];
            float sa = s_sa[row];
#pragma unroll
            for (int nf = 0; nf < 2; nf++) {
                int colloc = wn + nf * 8 + c2;
                int col = n0 + colloc;
                float su0 = sa * s_su[colloc], su1 = sa * s_su[colloc + 1];
                float sg0 = sa * s_sg[colloc], sg1 = sa * s_sg[colloc + 1];
                int idx = half * 2;
                float u0 = w * su0 * ((float)dU1[mi][nf][idx]     + 0.0078125f * (float)dU2[mi][nf][idx]);
                float u1 = w * su1 * ((float)dU1[mi][nf][idx + 1] + 0.0078125f * (float)dU2[mi][nf][idx + 1]);
                float gg0 = w * sg0 * ((float)dG1[mi][nf][idx]     + 0.0078125f * (float)dG2[mi][nf][idx]);
                float gg1 = w * sg1 * ((float)dG1[mi][nf][idx + 1] + 0.0078125f * (float)dG2[mi][nf][idx + 1]);
                float r0 = w * (gg0 / (1.f + __expf(-gg0))) * u0;
                float r1 = w * (gg1 / (1.f + __expf(-gg1))) * u1;
                *(float2*)&g_h[(size_t)gm * I_DIM + col] = make_float2(r0, r1);
            }
        }
    }

    // ---- fold: last of 8 n-tile CTAs quantizes each completed h row ----
    __shared__ unsigned char s_flag[64];
    __shared__ float s_wmax[2];
    __shared__ float s_qinv;
    __threadfence();          // this thread's g_h stores globally visible
    __syncthreads();          // => ALL threads' stores visible before any atomic below
    if (tid < 64) {
        s_flag[tid] = 0;
        int gm = m0 + tid;
        if (gm < mEnd) {
            int old = atomicAdd(&g_hcnt[gm], 1);
            if (old == 7) s_flag[tid] = 1;
        }
    }
    __syncthreads();
    for (int r = 0; r < 64; r++) {
        if (!s_flag[r]) continue;                 // uniform (smem)
        int gm = m0 + r;
        float v[8];
        float mx = 0.f;
        if (tid < 64) {
            const float4* p4 = (const float4*)&g_h[(size_t)gm * I_DIM + tid * 8];
            float4 a = __ldcg(p4);
            float4 b = __ldcg(p4 + 1);
            v[0] = a.x; v[1] = a.y; v[2] = a.z; v[3] = a.w;
            v[4] = b.x; v[5] = b.y; v[6] = b.z; v[7] = b.w;
#pragma unroll
            for (int j = 0; j < 8; j++) mx = fmaxf(mx, fabsf(v[j]));
#pragma unroll
            for (int o = 16; o; o >>= 1) mx = fmaxf(mx, __shfl_xor_sync(0xFFFFFFFFu, mx, o));
            if ((tid & 31) == 0) s_wmax[tid >> 5] = mx;
        }
        __syncthreads();
        if (tid == 0) {
            float mm = fmaxf(s_wmax[0], s_wmax[1]);
            g_sh[gm] = mm * (1.f / 127.f);
            s_qinv   = (mm > 0.f) ? (127.f / mm) : 0.f;
        }
        __syncthreads();
        if (tid < 64) {
            float inv = s_qinv;
            unsigned long long u1 = 0, u2 = 0;
#pragma unroll
            for (int j = 0; j < 8; j++) {
                float t  = v[j] * inv;
                float t1 = rintf(t);
                int c1 = (int)t1;
                int c2q = (int)rintf((t - t1) * 128.f);
                u1 |= ((unsigned long long)(unsigned char)(signed char)c1) << (8 * j);
                u2 |= ((unsigned long long)(unsigned char)(signed char)c2q) << (8 * j);
            }
            size_t o = (size_t)gm * I_DIM + tid * 8;
            *(unsigned long long*)(g_h1 + o) = u1;
            *(unsigned long long*)(g_h2 + o) = u2;
        }
        __syncthreads();
    }
}

// ============================================================================
// pass2: grouped int8 IMMA GEMM h @ w_down^T, CTA 64x64, K=512, two-level int8.
// Fold: last of 4 slot-contributors per (token, ntile) sums partials -> out.
// ============================================================================
#define P2_TILE  8192
#define P2_STAGE (4 * P2_TILE)                  // 32KB
#define P2_SMEM  (2048 + 2 * P2_STAGE)          // 67584 -> 3 CTAs/SM
#define P2_NC    4

__global__ void __launch_bounds__(256, 3) pass2_mma(float* __restrict__ out) {
    int e     = blockIdx.z;
    int mBase = g_offsets[e];
    int mEnd  = g_offsets[e + 1];
    int m0    = mBase + blockIdx.y * 64;
    if (m0 >= mEnd) return;
    int n0 = blockIdx.x * 64;

    extern __shared__ char smem[];
    int*   s_slot = (int*)smem;            // 64
    float* s_sa   = (float*)(smem + 256);  // 64
    float* s_sb   = (float*)(smem + 512);  // 64
    int*   s_row  = (int*)(smem + 768);    // 64
    uint32_t tb = smem_u32(smem + 2048);

    int tid = threadIdx.x, wid = tid >> 5, lane = tid & 31;
    for (int r = tid; r < 64; r += 256) {
        int gm = m0 + r;
        int rr = (gm < mEnd) ? gm : mBase;
        s_row[r]  = rr;
        s_slot[r] = (gm < mEnd) ? g_slot[gm] : 0;
        s_sa[r]   = g_sh[rr];
        s_sb[r]   = g_swd[e * H_DIM + n0 + r];
    }
    __syncthreads();

    int lrow = tid >> 2;
    int qp   = tid & 3;
    uint32_t rbase = (uint32_t)lrow * 128;
    uint32_t cswz  = (rbase >> 3) & 0x70;
    uint32_t d0 = rbase + (((uint32_t)(qp * 32)) ^ cswz);
    uint32_t d1 = rbase + (((uint32_t)(qp * 32 + 16)) ^ cswz);
    size_t aoff = (size_t)s_row[lrow] * I_DIM + qp * 32;
    size_t boff = ((size_t)e * H_DIM + n0 + lrow) * I_DIM + qp * 32;
    const signed char* sA1 = g_h1 + aoff;
    const signed char* sA2 = g_h2 + aoff;
    const signed char* sB1 = g_wd1 + boff;
    const signed char* sB2 = g_wd2 + boff;

    int d1a[2][2][4], d2a[2][2][4];
#pragma unroll
    for (int a = 0; a < 2; a++)
#pragma unroll
        for (int b = 0; b < 2; b++)
#pragma unroll
            for (int c = 0; c < 4; c++) { d1a[a][b][c] = 0; d2a[a][b][c] = 0; }

    int wm = (wid >> 2) * 32;
    int wn = (wid & 3) * 16;
    int lgrp = lane >> 3, lr = lane & 7;
    int rowA = wm + (lgrp & 1) * 8 + lr;
    int rowB = wn + (lgrp >> 1) * 8 + lr;
    int colA = (lgrp >> 1) * 16;
    int colB = (lgrp & 1) * 16;

    {
        uint32_t sb_ = tb;
        cp_async16(sb_ + d0, sA1);                 cp_async16(sb_ + d1, sA1 + 16);
        cp_async16(sb_ + P2_TILE + d0, sA2);       cp_async16(sb_ + P2_TILE + d1, sA2 + 16);
        cp_async16(sb_ + 2 * P2_TILE + d0, sB1);   cp_async16(sb_ + 2 * P2_TILE + d1, sB1 + 16);
        cp_async16(sb_ + 3 * P2_TILE + d0, sB2);   cp_async16(sb_ + 3 * P2_TILE + d1, sB2 + 16);
        asm volatile("cp.async.commit_group;" ::: "memory");
    }

    for (int c = 0; c < P2_NC; c++) {
        if (c + 1 < P2_NC) {
            int k0 = (c + 1) * 128;
            uint32_t sb_ = tb + ((c + 1) & 1) * P2_STAGE;
            cp_async16(sb_ + d0, sA1 + k0);                 cp_async16(sb_ + d1, sA1 + k0 + 16);
            cp_async16(sb_ + P2_TILE + d0, sA2 + k0);       cp_async16(sb_ + P2_TILE + d1, sA2 + k0 + 16);
            cp_async16(sb_ + 2 * P2_TILE + d0, sB1 + k0);   cp_async16(sb_ + 2 * P2_TILE + d1, sB1 + k0 + 16);
            cp_async16(sb_ + 3 * P2_TILE + d0, sB2 + k0);   cp_async16(sb_ + 3 * P2_TILE + d1, sB2 + k0 + 16);
            asm volatile("cp.async.commit_group;" ::: "memory");
            asm volatile("cp.async.wait_group 1;" ::: "memory");
        } else {
            asm volatile("cp.async.wait_group 0;" ::: "memory");
        }
        __syncthreads();

        uint32_t st = tb + (c & 1) * P2_STAGE;
        uint32_t a1 = st, a2 = st + P2_TILE;
        uint32_t b1 = st + 2 * P2_TILE, b2 = st + 3 * P2_TILE;

#pragma unroll
        for (int s = 0; s < 4; s++) {
            int kaB = s * 32 + colA;
            int kbB = s * 32 + colB;
            uint32_t A1f[2][4], A2f[2][4];
            ldmx4(A1f[0], a1 + SWZ(rowA * 128 + kaB));
            ldmx4(A1f[1], a1 + SWZ((rowA + 16) * 128 + kaB));
            ldmx4(A2f[0], a2 + SWZ(rowA * 128 + kaB));
            ldmx4(A2f[1], a2 + SWZ((rowA + 16) * 128 + kaB));
            uint32_t B1f[4], B2f[4];
            {
                uint32_t off = SWZ(rowB * 128 + kbB);
                ldmx4(B1f, b1 + off);
                ldmx4(B2f, b2 + off);
            }
#pragma unroll
            for (int mi = 0; mi < 2; mi++)
#pragma unroll
                for (int nf = 0; nf < 2; nf++)
                    imma16832(d1a[mi][nf], A1f[mi], B1f[nf * 2], B1f[nf * 2 + 1]);
#pragma unroll
            for (int mi = 0; mi < 2; mi++)
#pragma unroll
                for (int nf = 0; nf < 2; nf++)
                    imma16832(d2a[mi][nf], A1f[mi], B2f[nf * 2], B2f[nf * 2 + 1]);
#pragma unroll
            for (int mi = 0; mi < 2; mi++)
#pragma unroll
                for (int nf = 0; nf < 2; nf++)
                    imma16832(d2a[mi][nf], A2f[mi], B1f[nf * 2], B1f[nf * 2 + 1]);
        }
        __syncthreads();
    }

    int r4 = lane >> 2, c2 = (lane & 3) * 2;
#pragma unroll
    for (int mi = 0; mi < 2; mi++) {
#pragma unroll
        for (int half = 0; half < 2; half++) {
            int row = wm + mi * 16 + half * 8 + r4;
            int gm  = m0 + row;
            if (gm >= mEnd) continue;
            int slot = s_slot[row];
            float sa = s_sa[row];
#pragma unroll
            for (int nf = 0; nf < 2; nf++) {
                int colloc = wn + nf * 8 + c2;
                int col = n0 + colloc;
                float sb0 = sa * s_sb[colloc];
                float sb1 = sa * s_sb[colloc + 1];
                int idx = half * 2;
                float v0 = sb0 * ((float)d1a[mi][nf][idx]     + 0.0078125f * (float)d2a[mi][nf][idx]);
                float v1 = sb1 * ((float)d1a[mi][nf][idx + 1] + 0.0078125f * (float)d2a[mi][nf][idx + 1]);
                *(float2*)&g_part[(size_t)slot * H_DIM + col] = make_float2(v0, v1);
            }
        }
    }

    // ---- fold: last of 4 slot contributors per (token, ntile) sums -> out ----
    __threadfence();          // this thread's g_part stores visible
    __syncthreads();          // all threads' stores visible before atomics
    if (tid < 64) {
        int gm = m0 + tid;
        if (gm < mEnd) {
            int t = s_slot[tid] >> 2;
            int old = atomicAdd(&g_ocnt[t * 16 + blockIdx.x], 1);
            if (old == 3) {
                __threadfence();
                size_t base = (size_t)(t * TK) * H_DIM + n0;
                float* op = out + (size_t)t * H_DIM + n0;
#pragma unroll 4
                for (int j = 0; j < 16; j++) {
                    float4 s0 = __ldcg((const float4*)&g_part[base + 0 * H_DIM + j * 4]);
                    float4 s1 = __ldcg((const float4*)&g_part[base + 1 * H_DIM + j * 4]);
                    float4 s2 = __ldcg((const float4*)&g_part[base + 2 * H_DIM + j * 4]);
                    float4 s3 = __ldcg((const float4*)&g_part[base + 3 * H_DIM + j * 4]);
                    float4 s;
                    s.x = s0.x + s1.x + s2.x + s3.x;
                    s.y = s0.y + s1.y + s2.y + s3.y;
                    s.z = s0.z + s1.z + s2.z + s3.z;
                    s.w = s0.w + s1.w + s2.w + s3.w;
                    *(float4*)(op + j * 4) = s;
                }
            }
        }
    }
}

// ---------------- launch ----------------
extern "C" void kernel_launch(void* const* d_in, const int* in_sizes, int n_in,
                              void* d_out, int out_size)
{
    const float* x             = (const float*)d_in[0];
    const float* router_logits = (const float*)d_in[1];
    const float* w_up          = (const float*)d_in[2];
    const float* w_gate        = (const float*)d_in[3];
    const float* w_down        = (const float*)d_in[4];
    float* out = (float*)d_out;

    cudaFuncSetAttribute(pass1_mma, cudaFuncAttributeMaxDynamicSharedMemorySize, P1_SMEM);
    cudaFuncSetAttribute(pass2_mma, cudaFuncAttributeMaxDynamicSharedMemorySize, P2_SMEM);

    // #1 prep (routing + conversions + counter reset), #2 pass1 (+h quant fold),
    // #3 pass2 (+reduce fold)
    prep_kernel<<<NB_PREP, 512>>>(router_logits, x, w_up, w_gate, w_down);

    dim3 g1(I_DIM / 64, T_TOK / 64, NE);
    pass1_mma<<<g1, 256, P1_SMEM>>>();

    dim3 g2(H_DIM / 64, T_TOK / 64, NE);
    pass2_mma<<<g2, 256, P2_SMEM>>>(out);
}

// round 15
// speedup vs baseline: 1.5962x; 1.5962x over previous
#include <cuda_runtime.h>
#include <cuda_bf16.h>
#include <math.h>
#include <stdint.h>

// Problem constants
#define T_TOK 2048
#define H_DIM 1024
#define I_DIM 512
#define NE    16
#define TK    4
#define NPAIR (T_TOK * TK)   // 8192

// ---------------- scratch (device globals; no allocation) ----------------
__device__ int   g_offsets[NE + 1];
__device__ int   g_ids[NPAIR];
__device__ float g_wt[NPAIR];
__device__ int   g_slot[NPAIR];

// int8 two-level quantized pass1 inputs + per-row scales
__device__ __align__(16) signed char g_x1[T_TOK * H_DIM];
__device__ __align__(16) signed char g_x2[T_TOK * H_DIM];
__device__ __align__(16) signed char g_u1[NE * I_DIM * H_DIM];
__device__ __align__(16) signed char g_u2[NE * I_DIM * H_DIM];
__device__ __align__(16) signed char g_g1[NE * I_DIM * H_DIM];
__device__ __align__(16) signed char g_g2[NE * I_DIM * H_DIM];
__device__ float g_sx[T_TOK];
__device__ float g_su[NE * I_DIM];
__device__ float g_sg[NE * I_DIM];

// pass2 operands
__device__ __align__(16) float g_h[(size_t)NPAIR * I_DIM];
__device__ __align__(16) signed char g_h1[(size_t)NPAIR * I_DIM];
__device__ __align__(16) signed char g_h2[(size_t)NPAIR * I_DIM];
__device__ float g_sh[NPAIR];
__device__ __align__(16) signed char g_wd1[NE * H_DIM * I_DIM];
__device__ __align__(16) signed char g_wd2[NE * H_DIM * I_DIM];
__device__ float g_swd[NE * H_DIM];

__device__ __align__(16) float g_part[(size_t)NPAIR * H_DIM];   // 32 MB

// ---------------- helpers ----------------
__device__ __forceinline__ uint32_t smem_u32(const void* p) {
    uint32_t a;
    asm("{ .reg .u64 t; cvta.to.shared.u64 t, %1; cvt.u32.u64 %0, t; }" : "=r"(a) : "l"(p));
    return a;
}
__device__ __forceinline__ void cp_async16(uint32_t dst, const void* src) {
    asm volatile("cp.async.cg.shared.global [%0], [%1], 16;" :: "r"(dst), "l"(src));
}
__device__ __forceinline__ void ldmx4(uint32_t r[4], uint32_t addr) {
    asm volatile("ldmatrix.sync.aligned.m8n8.x4.shared.b16 {%0,%1,%2,%3}, [%4];"
                 : "=r"(r[0]), "=r"(r[1]), "=r"(r[2]), "=r"(r[3]) : "r"(addr));
}
__device__ __forceinline__ void imma16832(int d[4], const uint32_t a[4], uint32_t b0, uint32_t b1) {
    asm("mma.sync.aligned.m16n8k32.row.col.s32.s8.s8.s32 "
        "{%0,%1,%2,%3}, {%4,%5,%6,%7}, {%8,%9}, {%0,%1,%2,%3};"
        : "+r"(d[0]), "+r"(d[1]), "+r"(d[2]), "+r"(d[3])
        : "r"(a[0]), "r"(a[1]), "r"(a[2]), "r"(a[3]), "r"(b0), "r"(b1));
}
#define SWZ(o) ((o) ^ (((o) >> 3) & 0x70))

// ============================================================================
// prep kernel: block 0 = routing; blocks [1..NB_CONV1] = conv_int8 rows;
// remaining = conv_wd8 rows.
// ============================================================================
#define CONV8_ROWS (T_TOK + 2 * NE * I_DIM)
#define NB_CONV1   ((CONV8_ROWS + 3) / 4)
#define NB_WD      ((NE * H_DIM + 7) / 8)
#define NB_PREP    (1 + NB_CONV1 + NB_WD)

__global__ void __launch_bounds__(512) prep_kernel(const float* __restrict__ logits,
                                                   const float* __restrict__ x,
                                                   const float* __restrict__ wu,
                                                   const float* __restrict__ wg,
                                                   const float* __restrict__ wd) {
    int bid = blockIdx.x;
    int tid = threadIdx.x;

    if (bid == 0) {
        __shared__ int s_cnt[NE], s_cur[NE], s_off[NE + 1];
        if (tid < NE) { s_cnt[tid] = 0; s_cur[tid] = 0; }
        __syncthreads();
        for (int t = tid; t < T_TOK; t += 512) {
            float l[NE];
#pragma unroll
            for (int e = 0; e < NE; e++) l[e] = logits[t * NE + e];
            int ids[TK]; float vals[TK];
            unsigned mask = 0;
#pragma unroll
            for (int k = 0; k < TK; k++) {
                float best = -1e30f; int bi = 0;
#pragma unroll
                for (int e = 0; e < NE; e++)
                    if (!((mask >> e) & 1u) && l[e] > best) { best = l[e]; bi = e; }
                ids[k] = bi; vals[k] = best; mask |= (1u << bi);
            }
            float m = vals[0];
            float w[TK]; float s = 0.f;
#pragma unroll
            for (int k = 0; k < TK; k++) { w[k] = expf(vals[k] - m); s += w[k]; }
            float inv = 1.f / s;
#pragma unroll
            for (int k = 0; k < TK; k++) {
                g_ids[t * TK + k] = ids[k];
                g_wt[t * TK + k]  = w[k] * inv;
                atomicAdd(&s_cnt[ids[k]], 1);
            }
        }
        __syncthreads();
        if (tid == 0) {
            int acc = 0;
            s_off[0] = 0; g_offsets[0] = 0;
#pragma unroll
            for (int e = 0; e < NE; e++) {
                acc += s_cnt[e];
                s_off[e + 1] = acc;
                g_offsets[e + 1] = acc;
            }
        }
        __syncthreads();
        for (int t = tid; t < T_TOK; t += 512) {
#pragma unroll
            for (int k = 0; k < TK; k++) {
                int e = g_ids[t * TK + k];
                int pos = s_off[e] + atomicAdd(&s_cur[e], 1);
                g_slot[pos] = t * TK + k;
            }
        }
        return;
    }

    if (bid <= NB_CONV1) {
        int grp = tid >> 7;
        int lt  = tid & 127;
        int r = (bid - 1) * 4 + grp;
        bool active = r < CONV8_ROWS;

        const float* src = x; signed char* q1 = g_x1; signed char* q2 = g_x2; float* sc = g_sx; int row = 0;
        if (active) {
            if (r < T_TOK)                 { src = x;  q1 = g_x1; q2 = g_x2; sc = g_sx; row = r; }
            else if (r < T_TOK + NE*I_DIM) { src = wu; q1 = g_u1; q2 = g_u2; sc = g_su; row = r - T_TOK; }
            else                           { src = wg; q1 = g_g1; q2 = g_g2; sc = g_sg; row = r - T_TOK - NE*I_DIM; }
        }

        float v[8] = {0, 0, 0, 0, 0, 0, 0, 0};
        if (active) {
            const float4* p4 = (const float4*)(src + (size_t)row * H_DIM + lt * 8);
            float4 a = p4[0], b = p4[1];
            v[0] = a.x; v[1] = a.y; v[2] = a.z; v[3] = a.w;
            v[4] = b.x; v[5] = b.y; v[6] = b.z; v[7] = b.w;
        }
        float m = 0.f;
#pragma unroll
        for (int j = 0; j < 8; j++) m = fmaxf(m, fabsf(v[j]));
#pragma unroll
        for (int o = 16; o; o >>= 1) m = fmaxf(m, __shfl_xor_sync(0xFFFFFFFFu, m, o));
        __shared__ float sm1[16];
        __shared__ float s_inv1[4];
        if ((lt & 31) == 0) sm1[grp * 4 + (lt >> 5)] = m;
        __syncthreads();
        if (lt == 0) {
            float mm = fmaxf(fmaxf(sm1[grp * 4], sm1[grp * 4 + 1]),
                             fmaxf(sm1[grp * 4 + 2], sm1[grp * 4 + 3]));
            if (active) sc[row] = mm * (1.f / 127.f);
            s_inv1[grp] = (mm > 0.f) ? (127.f / mm) : 0.f;
        }
        __syncthreads();
        if (!active) return;
        float inv = s_inv1[grp];
        unsigned long long u1 = 0, u2 = 0;
#pragma unroll
        for (int j = 0; j < 8; j++) {
            float t  = v[j] * inv;
            float t1 = rintf(t);
            int c1 = (int)t1;
            int c2 = (int)rintf((t - t1) * 128.f);
            u1 |= ((unsigned long long)(unsigned char)(signed char)c1) << (8 * j);
            u2 |= ((unsigned long long)(unsigned char)(signed char)c2) << (8 * j);
        }
        size_t o = (size_t)row * H_DIM + lt * 8;
        *(unsigned long long*)(q1 + o) = u1;
        *(unsigned long long*)(q2 + o) = u2;
        return;
    }

    {
        int grp = tid >> 6;
        int lt  = tid & 63;
        int row = (bid - 1 - NB_CONV1) * 8 + grp;
        bool active = row < NE * H_DIM;

        float v[8] = {0, 0, 0, 0, 0, 0, 0, 0};
        if (active) {
            const float4* p4 = (const float4*)(wd + (size_t)row * I_DIM + lt * 8);
            float4 a = p4[0], b = p4[1];
            v[0] = a.x; v[1] = a.y; v[2] = a.z; v[3] = a.w;
            v[4] = b.x; v[5] = b.y; v[6] = b.z; v[7] = b.w;
        }
        float m = 0.f;
#pragma unroll
        for (int j = 0; j < 8; j++) m = fmaxf(m, fabsf(v[j]));
#pragma unroll
        for (int o = 16; o; o >>= 1) m = fmaxf(m, __shfl_xor_sync(0xFFFFFFFFu, m, o));
        __shared__ float sm2[16];
        __shared__ float s_inv2[8];
        if ((lt & 31) == 0) sm2[grp * 2 + (lt >> 5)] = m;
        __syncthreads();
        if (lt == 0) {
            float mm = fmaxf(sm2[grp * 2], sm2[grp * 2 + 1]);
            if (active) g_swd[row] = mm * (1.f / 127.f);
            s_inv2[grp] = (mm > 0.f) ? (127.f / mm) : 0.f;
        }
        __syncthreads();
        if (!active) return;
        float inv = s_inv2[grp];
        unsigned long long u1 = 0, u2 = 0;
#pragma unroll
        for (int j = 0; j < 8; j++) {
            float t  = v[j] * inv;
            float t1 = rintf(t);
            int c1 = (int)t1;
            int c2 = (int)rintf((t - t1) * 128.f);
            u1 |= ((unsigned long long)(unsigned char)(signed char)c1) << (8 * j);
            u2 |= ((unsigned long long)(unsigned char)(signed char)c2) << (8 * j);
        }
        size_t o = (size_t)row * I_DIM + lt * 8;
        *(unsigned long long*)(g_wd1 + o) = u1;
        *(unsigned long long*)(g_wd2 + o) = u2;
    }
}

// ---------------- quant_h: rows of 512, 8 rows per block ----------------
__global__ void __launch_bounds__(512) quant_h_kernel() {
    int grp = threadIdx.x >> 6;
    int lt  = threadIdx.x & 63;
    int row = blockIdx.x * 8 + grp;
    bool active = row < NPAIR;

    float v[8] = {0, 0, 0, 0, 0, 0, 0, 0};
    if (active) {
        const float4* p4 = (const float4*)(g_h + (size_t)row * I_DIM + lt * 8);
        float4 a = p4[0], b = p4[1];
        v[0] = a.x; v[1] = a.y; v[2] = a.z; v[3] = a.w;
        v[4] = b.x; v[5] = b.y; v[6] = b.z; v[7] = b.w;
    }
    float m = 0.f;
#pragma unroll
    for (int j = 0; j < 8; j++) m = fmaxf(m, fabsf(v[j]));
#pragma unroll
    for (int o = 16; o; o >>= 1) m = fmaxf(m, __shfl_xor_sync(0xFFFFFFFFu, m, o));
    __shared__ float sm[16];
    __shared__ float s_inv[8];
    if ((lt & 31) == 0) sm[grp * 2 + (lt >> 5)] = m;
    __syncthreads();
    if (lt == 0) {
        float mm = fmaxf(sm[grp * 2], sm[grp * 2 + 1]);
        if (active) g_sh[row] = mm * (1.f / 127.f);
        s_inv[grp] = (mm > 0.f) ? (127.f / mm) : 0.f;
    }
    __syncthreads();
    if (!active) return;
    float inv = s_inv[grp];
    unsigned long long u1 = 0, u2 = 0;
#pragma unroll
    for (int j = 0; j < 8; j++) {
        float t  = v[j] * inv;
        float t1 = rintf(t);
        int c1 = (int)t1;
        int c2 = (int)rintf((t - t1) * 128.f);
        u1 |= ((unsigned long long)(unsigned char)(signed char)c1) << (8 * j);
        u2 |= ((unsigned long long)(unsigned char)(signed char)c2) << (8 * j);
    }
    size_t o = (size_t)row * I_DIM + lt * 8;
    *(unsigned long long*)(g_h1 + o) = u1;
    *(unsigned long long*)(g_h2 + o) = u2;
}

// ============================================================================
// pass1: grouped int8 IMMA GEMM, CTA 64x64, K=1024, fused up+gate,
// two-level int8 (3-term). Dual-sync 2-stage pipeline (proven).
// ============================================================================
#define P1_TILE  8192
#define P1_STAGE (6 * P1_TILE)                  // 48KB
#define P1_SMEM  (2048 + 2 * P1_STAGE)          // 100352 -> 2 CTAs/SM
#define P1_NC    8

__global__ void __launch_bounds__(256, 2) pass1_mma() {
    int e     = blockIdx.z;
    int mBase = g_offsets[e];
    int mEnd  = g_offsets[e + 1];
    int m0    = mBase + blockIdx.y * 64;
    if (m0 >= mEnd) return;
    int n0 = blockIdx.x * 64;

    extern __shared__ char smem[];
    int*   s_tok = (int*)smem;
    float* s_wt  = (float*)(smem + 256);
    float* s_sa  = (float*)(smem + 512);
    float* s_su  = (float*)(smem + 768);
    float* s_sg  = (float*)(smem + 1024);
    uint32_t tb  = smem_u32(smem + 2048);

    int tid = threadIdx.x, wid = tid >> 5, lane = tid & 31;
    for (int r = tid; r < 64; r += 256) {
        int gm = m0 + r;
        int slot = (gm < mEnd) ? g_slot[gm] : g_slot[mBase];
        int tok = slot >> 2;
        s_tok[r] = tok;
        s_wt[r]  = g_wt[slot];
        s_sa[r]  = g_sx[tok];
        s_su[r]  = g_su[e * I_DIM + n0 + r];
        s_sg[r]  = g_sg[e * I_DIM + n0 + r];
    }
    __syncthreads();

    int lrow = tid >> 2;
    int qp   = tid & 3;
    uint32_t rbase = (uint32_t)lrow * 128;
    uint32_t cswz  = (rbase >> 3) & 0x70;
    uint32_t d0 = rbase + (((uint32_t)(qp * 32)) ^ cswz);
    uint32_t d1 = rbase + (((uint32_t)(qp * 32 + 16)) ^ cswz);
    size_t aoff = (size_t)s_tok[lrow] * H_DIM + qp * 32;
    size_t boff = ((size_t)e * I_DIM + n0 + lrow) * H_DIM + qp * 32;
    const signed char* sA1 = g_x1 + aoff;
    const signed char* sA2 = g_x2 + aoff;
    const signed char* sU1 = g_u1 + boff;
    const signed char* sU2 = g_u2 + boff;
    const signed char* sG1 = g_g1 + boff;
    const signed char* sG2 = g_g2 + boff;

    int dU1[2][2][4], dU2[2][2][4], dG1[2][2][4], dG2[2][2][4];
#pragma unroll
    for (int a = 0; a < 2; a++)
#pragma unroll
        for (int b = 0; b < 2; b++)
#pragma unroll
            for (int c = 0; c < 4; c++) {
                dU1[a][b][c] = 0; dU2[a][b][c] = 0;
                dG1[a][b][c] = 0; dG2[a][b][c] = 0;
            }

    int wm = (wid >> 2) * 32;
    int wn = (wid & 3) * 16;
    int lgrp = lane >> 3, lr = lane & 7;
    int rowA = wm + (lgrp & 1) * 8 + lr;
    int rowB = wn + (lgrp >> 1) * 8 + lr;
    int colA = (lgrp >> 1) * 16;
    int colB = (lgrp & 1) * 16;

    {
        uint32_t sb_ = tb;
        cp_async16(sb_ + d0, sA1);                   cp_async16(sb_ + d1, sA1 + 16);
        cp_async16(sb_ + P1_TILE + d0, sA2);         cp_async16(sb_ + P1_TILE + d1, sA2 + 16);
        cp_async16(sb_ + 2 * P1_TILE + d0, sU1);     cp_async16(sb_ + 2 * P1_TILE + d1, sU1 + 16);
        cp_async16(sb_ + 3 * P1_TILE + d0, sU2);     cp_async16(sb_ + 3 * P1_TILE + d1, sU2 + 16);
        cp_async16(sb_ + 4 * P1_TILE + d0, sG1);     cp_async16(sb_ + 4 * P1_TILE + d1, sG1 + 16);
        cp_async16(sb_ + 5 * P1_TILE + d0, sG2);     cp_async16(sb_ + 5 * P1_TILE + d1, sG2 + 16);
        asm volatile("cp.async.commit_group;" ::: "memory");
    }

    for (int c = 0; c < P1_NC; c++) {
        if (c + 1 < P1_NC) {
            int k0 = (c + 1) * 128;
            uint32_t sb_ = tb + ((c + 1) & 1) * P1_STAGE;
            cp_async16(sb_ + d0, sA1 + k0);                cp_async16(sb_ + d1, sA1 + k0 + 16);
            cp_async16(sb_ + P1_TILE + d0, sA2 + k0);      cp_async16(sb_ + P1_TILE + d1, sA2 + k0 + 16);
            cp_async16(sb_ + 2 * P1_TILE + d0, sU1 + k0);  cp_async16(sb_ + 2 * P1_TILE + d1, sU1 + k0 + 16);
            cp_async16(sb_ + 3 * P1_TILE + d0, sU2 + k0);  cp_async16(sb_ + 3 * P1_TILE + d1, sU2 + k0 + 16);
            cp_async16(sb_ + 4 * P1_TILE + d0, sG1 + k0);  cp_async16(sb_ + 4 * P1_TILE + d1, sG1 + k0 + 16);
            cp_async16(sb_ + 5 * P1_TILE + d0, sG2 + k0);  cp_async16(sb_ + 5 * P1_TILE + d1, sG2 + k0 + 16);
            asm volatile("cp.async.commit_group;" ::: "memory");
            asm volatile("cp.async.wait_group 1;" ::: "memory");
        } else {
            asm volatile("cp.async.wait_group 0;" ::: "memory");
        }
        __syncthreads();

        uint32_t st = tb + (c & 1) * P1_STAGE;
        uint32_t aQ1 = st, aQ2 = st + P1_TILE;
        uint32_t bU1 = st + 2 * P1_TILE, bU2 = st + 3 * P1_TILE;
        uint32_t bG1 = st + 4 * P1_TILE, bG2 = st + 5 * P1_TILE;

#pragma unroll
        for (int s = 0; s < 4; s++) {
            int kaB = s * 32 + colA;
            int kbB = s * 32 + colB;
            uint32_t A1f[2][4], A2f[2][4];
            ldmx4(A1f[0], aQ1 + SWZ(rowA * 128 + kaB));
            ldmx4(A1f[1], aQ1 + SWZ((rowA + 16) * 128 + kaB));
            ldmx4(A2f[0], aQ2 + SWZ(rowA * 128 + kaB));
            ldmx4(A2f[1], aQ2 + SWZ((rowA + 16) * 128 + kaB));
            uint32_t U1f[4], U2f[4], G1f[4], G2f[4];
            {
                uint32_t off = SWZ(rowB * 128 + kbB);
                ldmx4(U1f, bU1 + off);
                ldmx4(U2f, bU2 + off);
                ldmx4(G1f, bG1 + off);
                ldmx4(G2f, bG2 + off);
            }
#pragma unroll
            for (int mi = 0; mi < 2; mi++)
#pragma unroll
                for (int nf = 0; nf < 2; nf++) {
                    imma16832(dU1[mi][nf], A1f[mi], U1f[nf * 2], U1f[nf * 2 + 1]);
                    imma16832(dG1[mi][nf], A1f[mi], G1f[nf * 2], G1f[nf * 2 + 1]);
                }
#pragma unroll
            for (int mi = 0; mi < 2; mi++)
#pragma unroll
                for (int nf = 0; nf < 2; nf++) {
                    imma16832(dU2[mi][nf], A1f[mi], U2f[nf * 2], U2f[nf * 2 + 1]);
                    imma16832(dG2[mi][nf], A1f[mi], G2f[nf * 2], G2f[nf * 2 + 1]);
                }
#pragma unroll
            for (int mi = 0; mi < 2; mi++)
#pragma unroll
                for (int nf = 0; nf < 2; nf++) {
                    imma16832(dU2[mi][nf], A2f[mi], U1f[nf * 2], U1f[nf * 2 + 1]);
                    imma16832(dG2[mi][nf], A2f[mi], G1f[nf * 2], G1f[nf * 2 + 1]);
                }
        }
        __syncthreads();
    }

    // ---- epilogue ----
    int r4 = lane >> 2, c2 = (lane & 3) * 2;
#pragma unroll
    for (int mi = 0; mi < 2; mi++) {
#pragma unroll
        for (int half = 0; half < 2; half++) {
            int row = wm + mi * 16 + half * 8 + r4;
            int gm  = m0 + row;
            if (gm >= mEnd) continue;
            float w  = s_wt[row];
            float sa = s_sa[row];
#pragma unroll
            for (int nf = 0; nf < 2; nf++) {
                int colloc = wn + nf * 8 + c2;
                int col = n0 + colloc;
                float su0 = sa * s_su[colloc], su1 = sa * s_su[colloc + 1];
                float sg0 = sa * s_sg[colloc], sg1 = sa * s_sg[colloc + 1];
                int idx = half * 2;
                float u0 = w * su0 * ((float)dU1[mi][nf][idx]     + 0.0078125f * (float)dU2[mi][nf][idx]);
                float u1 = w * su1 * ((float)dU1[mi][nf][idx + 1] + 0.0078125f * (float)dU2[mi][nf][idx + 1]);
                float gg0 = w * sg0 * ((float)dG1[mi][nf][idx]     + 0.0078125f * (float)dG2[mi][nf][idx]);
                float gg1 = w * sg1 * ((float)dG1[mi][nf][idx + 1] + 0.0078125f * (float)dG2[mi][nf][idx + 1]);
                float r0 = w * (gg0 / (1.f + __expf(-gg0))) * u0;
                float r1 = w * (gg1 / (1.f + __expf(-gg1))) * u1;
                *(float2*)&g_h[(size_t)gm * I_DIM + col] = make_float2(r0, r1);
            }
        }
    }
}

// ============================================================================
// pass2: grouped int8 IMMA GEMM h @ w_down^T, CTA 64x64, K=512, two-level int8.
// 4 tiles/stage = 32KB; 2 stages = 66KB -> 3 CTAs/SM (24 warps).
// ============================================================================
#define P2_TILE  8192
#define P2_STAGE (4 * P2_TILE)                  // 32KB
#define P2_SMEM  (2048 + 2 * P2_STAGE)          // 67584 -> 3 CTAs/SM
#define P2_NC    4

__global__ void __launch_bounds__(256, 3) pass2_mma() {
    int e     = blockIdx.z;
    int mBase = g_offsets[e];
    int mEnd  = g_offsets[e + 1];
    int m0    = mBase + blockIdx.y * 64;
    if (m0 >= mEnd) return;
    int n0 = blockIdx.x * 64;

    extern __shared__ char smem[];
    int*   s_slot = (int*)smem;            // 64
    float* s_sa   = (float*)(smem + 256);  // 64
    float* s_sb   = (float*)(smem + 512);  // 64
    int*   s_row  = (int*)(smem + 768);    // 64
    uint32_t tb = smem_u32(smem + 2048);

    int tid = threadIdx.x, wid = tid >> 5, lane = tid & 31;
    for (int r = tid; r < 64; r += 256) {
        int gm = m0 + r;
        int rr = (gm < mEnd) ? gm : mBase;
        s_row[r]  = rr;
        s_slot[r] = (gm < mEnd) ? g_slot[gm] : 0;
        s_sa[r]   = g_sh[rr];
        s_sb[r]   = g_swd[e * H_DIM + n0 + r];
    }
    __syncthreads();

    int lrow = tid >> 2;
    int qp   = tid & 3;
    uint32_t rbase = (uint32_t)lrow * 128;
    uint32_t cswz  = (rbase >> 3) & 0x70;
    uint32_t d0 = rbase + (((uint32_t)(qp * 32)) ^ cswz);
    uint32_t d1 = rbase + (((uint32_t)(qp * 32 + 16)) ^ cswz);
    size_t aoff = (size_t)s_row[lrow] * I_DIM + qp * 32;
    size_t boff = ((size_t)e * H_DIM + n0 + lrow) * I_DIM + qp * 32;
    const signed char* sA1 = g_h1 + aoff;
    const signed char* sA2 = g_h2 + aoff;
    const signed char* sB1 = g_wd1 + boff;
    const signed char* sB2 = g_wd2 + boff;

    int d1a[2][2][4], d2a[2][2][4];
#pragma unroll
    for (int a = 0; a < 2; a++)
#pragma unroll
        for (int b = 0; b < 2; b++)
#pragma unroll
            for (int c = 0; c < 4; c++) { d1a[a][b][c] = 0; d2a[a][b][c] = 0; }

    int wm = (wid >> 2) * 32;
    int wn = (wid & 3) * 16;
    int lgrp = lane >> 3, lr = lane & 7;
    int rowA = wm + (lgrp & 1) * 8 + lr;
    int rowB = wn + (lgrp >> 1) * 8 + lr;
    int colA = (lgrp >> 1) * 16;
    int colB = (lgrp & 1) * 16;

    {
        uint32_t sb_ = tb;
        cp_async16(sb_ + d0, sA1);                 cp_async16(sb_ + d1, sA1 + 16);
        cp_async16(sb_ + P2_TILE + d0, sA2);       cp_async16(sb_ + P2_TILE + d1, sA2 + 16);
        cp_async16(sb_ + 2 * P2_TILE + d0, sB1);   cp_async16(sb_ + 2 * P2_TILE + d1, sB1 + 16);
        cp_async16(sb_ + 3 * P2_TILE + d0, sB2);   cp_async16(sb_ + 3 * P2_TILE + d1, sB2 + 16);
        asm volatile("cp.async.commit_group;" ::: "memory");
    }

    for (int c = 0; c < P2_NC; c++) {
        if (c + 1 < P2_NC) {
            int k0 = (c + 1) * 128;
            uint32_t sb_ = tb + ((c + 1) & 1) * P2_STAGE;
            cp_async16(sb_ + d0, sA1 + k0);                 cp_async16(sb_ + d1, sA1 + k0 + 16);
            cp_async16(sb_ + P2_TILE + d0, sA2 + k0);       cp_async16(sb_ + P2_TILE + d1, sA2 + k0 + 16);
            cp_async16(sb_ + 2 * P2_TILE + d0, sB1 + k0);   cp_async16(sb_ + 2 * P2_TILE + d1, sB1 + k0 + 16);
            cp_async16(sb_ + 3 * P2_TILE + d0, sB2 + k0);   cp_async16(sb_ + 3 * P2_TILE + d1, sB2 + k0 + 16);
            asm volatile("cp.async.commit_group;" ::: "memory");
            asm volatile("cp.async.wait_group 1;" ::: "memory");
        } else {
            asm volatile("cp.async.wait_group 0;" ::: "memory");
        }
        __syncthreads();

        uint32_t st = tb + (c & 1) * P2_STAGE;
        uint32_t a1 = st, a2 = st + P2_TILE;
        uint32_t b1 = st + 2 * P2_TILE, b2 = st + 3 * P2_TILE;

#pragma unroll
        for (int s = 0; s < 4; s++) {
            int kaB = s * 32 + colA;
            int kbB = s * 32 + colB;
            uint32_t A1f[2][4], A2f[2][4];
            ldmx4(A1f[0], a1 + SWZ(rowA * 128 + kaB));
            ldmx4(A1f[1], a1 + SWZ((rowA + 16) * 128 + kaB));
            ldmx4(A2f[0], a2 + SWZ(rowA * 128 + kaB));
            ldmx4(A2f[1], a2 + SWZ((rowA + 16) * 128 + kaB));
            uint32_t B1f[4], B2f[4];
            {
                uint32_t off = SWZ(rowB * 128 + kbB);
                ldmx4(B1f, b1 + off);
                ldmx4(B2f, b2 + off);
            }
#pragma unroll
            for (int mi = 0; mi < 2; mi++)
#pragma unroll
                for (int nf = 0; nf < 2; nf++)
                    imma16832(d1a[mi][nf], A1f[mi], B1f[nf * 2], B1f[nf * 2 + 1]);
#pragma unroll
            for (int mi = 0; mi < 2; mi++)
#pragma unroll
                for (int nf = 0; nf < 2; nf++)
                    imma16832(d2a[mi][nf], A1f[mi], B2f[nf * 2], B2f[nf * 2 + 1]);
#pragma unroll
            for (int mi = 0; mi < 2; mi++)
#pragma unroll
                for (int nf = 0; nf < 2; nf++)
                    imma16832(d2a[mi][nf], A2f[mi], B1f[nf * 2], B1f[nf * 2 + 1]);
        }
        __syncthreads();
    }

    int r4 = lane >> 2, c2 = (lane & 3) * 2;
#pragma unroll
    for (int mi = 0; mi < 2; mi++) {
#pragma unroll
        for (int half = 0; half < 2; half++) {
            int row = wm + mi * 16 + half * 8 + r4;
            int gm  = m0 + row;
            if (gm >= mEnd) continue;
            int slot = s_slot[row];
            float sa = s_sa[row];
#pragma unroll
            for (int nf = 0; nf < 2; nf++) {
                int colloc = wn + nf * 8 + c2;
                int col = n0 + colloc;
                float sb0 = sa * s_sb[colloc];
                float sb1 = sa * s_sb[colloc + 1];
                int idx = half * 2;
                float v0 = sb0 * ((float)d1a[mi][nf][idx]     + 0.0078125f * (float)d2a[mi][nf][idx]);
                float v1 = sb1 * ((float)d1a[mi][nf][idx + 1] + 0.0078125f * (float)d2a[mi][nf][idx + 1]);
                *(float2*)&g_part[(size_t)slot * H_DIM + col] = make_float2(v0, v1);
            }
        }
    }
}

// ---------------- reduce: 2 outputs/thread ----------------
__global__ void __launch_bounds__(256) reduce_kernel(float* __restrict__ out) {
    int i0 = (blockIdx.x * blockDim.x + threadIdx.x) * 2;
    int total = T_TOK * H_DIM / 4;
    if (i0 >= total) return;
#pragma unroll
    for (int u = 0; u < 2; u++) {
        int i = i0 + u;
        if (i >= total) break;
        int t  = i / (H_DIM / 4);
        int hc = (i % (H_DIM / 4)) * 4;
        float4 s = make_float4(0.f, 0.f, 0.f, 0.f);
#pragma unroll
        for (int k = 0; k < TK; k++) {
            float4 v = *(const float4*)&g_part[(size_t)(t * TK + k) * H_DIM + hc];
            s.x += v.x; s.y += v.y; s.z += v.z; s.w += v.w;
        }
        *(float4*)&out[(size_t)t * H_DIM + hc] = s;
    }
}

// ---------------- launch ----------------
extern "C" void kernel_launch(void* const* d_in, const int* in_sizes, int n_in,
                              void* d_out, int out_size)
{
    const float* x             = (const float*)d_in[0];
    const float* router_logits = (const float*)d_in[1];
    const float* w_up          = (const float*)d_in[2];
    const float* w_gate        = (const float*)d_in[3];
    const float* w_down        = (const float*)d_in[4];
    float* out = (float*)d_out;

    cudaFuncSetAttribute(pass1_mma, cudaFuncAttributeMaxDynamicSharedMemorySize, P1_SMEM);
    cudaFuncSetAttribute(pass2_mma, cudaFuncAttributeMaxDynamicSharedMemorySize, P2_SMEM);

    // #1 prep, #2 pass1, #3 quant_h, #4 pass2 (profiled), #5 reduce
    prep_kernel<<<NB_PREP, 512>>>(router_logits, x, w_up, w_gate, w_down);

    dim3 g1(I_DIM / 64, T_TOK / 64, NE);
    pass1_mma<<<g1, 256, P1_SMEM>>>();

    quant_h_kernel<<<(NPAIR + 7) / 8, 512>>>();

    dim3 g2(H_DIM / 64, T_TOK / 64, NE);
    pass2_mma<<<g2, 256, P2_SMEM>>>();

    reduce_kernel<<<(T_TOK * H_DIM / 8 + 255) / 256, 256>>>(out);
}

// round 17
// speedup vs baseline: 1.6303x; 1.0214x over previous
#include <cuda_runtime.h>
#include <cuda_bf16.h>
#include <math.h>
#include <stdint.h>

// Problem constants
#define T_TOK 2048
#define H_DIM 1024
#define I_DIM 512
#define NE    16
#define TK    4
#define NPAIR (T_TOK * TK)   // 8192

// ---------------- scratch (device globals; no allocation) ----------------
__device__ int   g_offsets[NE + 1];
__device__ int   g_ids[NPAIR];
__device__ float g_wt[NPAIR];
__device__ int   g_slot[NPAIR];

// int8 two-level quantized pass1 inputs + per-row scales
__device__ __align__(16) signed char g_x1[T_TOK * H_DIM];
__device__ __align__(16) signed char g_x2[T_TOK * H_DIM];
__device__ __align__(16) signed char g_u1[NE * I_DIM * H_DIM];
__device__ __align__(16) signed char g_u2[NE * I_DIM * H_DIM];
__device__ __align__(16) signed char g_g1[NE * I_DIM * H_DIM];
__device__ __align__(16) signed char g_g2[NE * I_DIM * H_DIM];
__device__ float g_sx[T_TOK];
__device__ float g_su[NE * I_DIM];
__device__ float g_sg[NE * I_DIM];

// pass2 operands
__device__ __align__(16) float g_h[(size_t)NPAIR * I_DIM];
__device__ __align__(16) signed char g_h1[(size_t)NPAIR * I_DIM];
__device__ __align__(16) signed char g_h2[(size_t)NPAIR * I_DIM];
__device__ float g_sh[NPAIR];
__device__ __align__(16) signed char g_wd1[NE * H_DIM * I_DIM];
__device__ __align__(16) signed char g_wd2[NE * H_DIM * I_DIM];
__device__ float g_swd[NE * H_DIM];

// ---------------- helpers ----------------
__device__ __forceinline__ uint32_t smem_u32(const void* p) {
    uint32_t a;
    asm("{ .reg .u64 t; cvta.to.shared.u64 t, %1; cvt.u32.u64 %0, t; }" : "=r"(a) : "l"(p));
    return a;
}
__device__ __forceinline__ void cp_async16(uint32_t dst, const void* src) {
    asm volatile("cp.async.cg.shared.global [%0], [%1], 16;" :: "r"(dst), "l"(src));
}
__device__ __forceinline__ void ldmx4(uint32_t r[4], uint32_t addr) {
    asm volatile("ldmatrix.sync.aligned.m8n8.x4.shared.b16 {%0,%1,%2,%3}, [%4];"
                 : "=r"(r[0]), "=r"(r[1]), "=r"(r[2]), "=r"(r[3]) : "r"(addr));
}
__device__ __forceinline__ void imma16832(int d[4], const uint32_t a[4], uint32_t b0, uint32_t b1) {
    asm("mma.sync.aligned.m16n8k32.row.col.s32.s8.s8.s32 "
        "{%0,%1,%2,%3}, {%4,%5,%6,%7}, {%8,%9}, {%0,%1,%2,%3};"
        : "+r"(d[0]), "+r"(d[1]), "+r"(d[2]), "+r"(d[3])
        : "r"(a[0]), "r"(a[1]), "r"(a[2]), "r"(a[3]), "r"(b0), "r"(b1));
}
__device__ __forceinline__ void red_add_f32(float* p, float v) {
    asm volatile("red.global.add.f32 [%0], %1;" :: "l"(p), "f"(v) : "memory");
}
#define SWZ(o) ((o) ^ (((o) >> 3) & 0x70))

// ============================================================================
// prep kernel: block 0 = routing; blocks [1..NB_CONV1] = conv_int8 rows;
// next NB_WD = conv_wd8 rows; last NB_OUT = zero the output buffer.
// ============================================================================
#define CONV8_ROWS (T_TOK + 2 * NE * I_DIM)
#define NB_CONV1   ((CONV8_ROWS + 3) / 4)
#define NB_WD      ((NE * H_DIM + 7) / 8)
#define NB_OUT     (T_TOK * H_DIM / 4 / 512)     // 1024 blocks, 1 float4/thread
#define NB_PREP    (1 + NB_CONV1 + NB_WD + NB_OUT)

__global__ void __launch_bounds__(512) prep_kernel(const float* __restrict__ logits,
                                                   const float* __restrict__ x,
                                                   const float* __restrict__ wu,
                                                   const float* __restrict__ wg,
                                                   const float* __restrict__ wd,
                                                   float* __restrict__ out) {
    int bid = blockIdx.x;
    int tid = threadIdx.x;

    if (bid == 0) {
        __shared__ int s_cnt[NE], s_cur[NE], s_off[NE + 1];
        if (tid < NE) { s_cnt[tid] = 0; s_cur[tid] = 0; }
        __syncthreads();
        for (int t = tid; t < T_TOK; t += 512) {
            float l[NE];
#pragma unroll
            for (int e = 0; e < NE; e++) l[e] = logits[t * NE + e];
            int ids[TK]; float vals[TK];
            unsigned mask = 0;
#pragma unroll
            for (int k = 0; k < TK; k++) {
                float best = -1e30f; int bi = 0;
#pragma unroll
                for (int e = 0; e < NE; e++)
                    if (!((mask >> e) & 1u) && l[e] > best) { best = l[e]; bi = e; }
                ids[k] = bi; vals[k] = best; mask |= (1u << bi);
            }
            float m = vals[0];
            float w[TK]; float s = 0.f;
#pragma unroll
            for (int k = 0; k < TK; k++) { w[k] = expf(vals[k] - m); s += w[k]; }
            float inv = 1.f / s;
#pragma unroll
            for (int k = 0; k < TK; k++) {
                g_ids[t * TK + k] = ids[k];
                g_wt[t * TK + k]  = w[k] * inv;
                atomicAdd(&s_cnt[ids[k]], 1);
            }
        }
        __syncthreads();
        if (tid == 0) {
            int acc = 0;
            s_off[0] = 0; g_offsets[0] = 0;
#pragma unroll
            for (int e = 0; e < NE; e++) {
                acc += s_cnt[e];
                s_off[e + 1] = acc;
                g_offsets[e + 1] = acc;
            }
        }
        __syncthreads();
        for (int t = tid; t < T_TOK; t += 512) {
#pragma unroll
            for (int k = 0; k < TK; k++) {
                int e = g_ids[t * TK + k];
                int pos = s_off[e] + atomicAdd(&s_cur[e], 1);
                g_slot[pos] = t * TK + k;
            }
        }
        return;
    }

    if (bid <= NB_CONV1) {
        int grp = tid >> 7;
        int lt  = tid & 127;
        int r = (bid - 1) * 4 + grp;
        bool active = r < CONV8_ROWS;

        const float* src = x; signed char* q1 = g_x1; signed char* q2 = g_x2; float* sc = g_sx; int row = 0;
        if (active) {
            if (r < T_TOK)                 { src = x;  q1 = g_x1; q2 = g_x2; sc = g_sx; row = r; }
            else if (r < T_TOK + NE*I_DIM) { src = wu; q1 = g_u1; q2 = g_u2; sc = g_su; row = r - T_TOK; }
            else                           { src = wg; q1 = g_g1; q2 = g_g2; sc = g_sg; row = r - T_TOK - NE*I_DIM; }
        }

        float v[8] = {0, 0, 0, 0, 0, 0, 0, 0};
        if (active) {
            const float4* p4 = (const float4*)(src + (size_t)row * H_DIM + lt * 8);
            float4 a = p4[0], b = p4[1];
            v[0] = a.x; v[1] = a.y; v[2] = a.z; v[3] = a.w;
            v[4] = b.x; v[5] = b.y; v[6] = b.z; v[7] = b.w;
        }
        float m = 0.f;
#pragma unroll
        for (int j = 0; j < 8; j++) m = fmaxf(m, fabsf(v[j]));
#pragma unroll
        for (int o = 16; o; o >>= 1) m = fmaxf(m, __shfl_xor_sync(0xFFFFFFFFu, m, o));
        __shared__ float sm1[16];
        __shared__ float s_inv1[4];
        if ((lt & 31) == 0) sm1[grp * 4 + (lt >> 5)] = m;
        __syncthreads();
        if (lt == 0) {
            float mm = fmaxf(fmaxf(sm1[grp * 4], sm1[grp * 4 + 1]),
                             fmaxf(sm1[grp * 4 + 2], sm1[grp * 4 + 3]));
            if (active) sc[row] = mm * (1.f / 127.f);
            s_inv1[grp] = (mm > 0.f) ? (127.f / mm) : 0.f;
        }
        __syncthreads();
        if (!active) return;
        float inv = s_inv1[grp];
        unsigned long long u1 = 0, u2 = 0;
#pragma unroll
        for (int j = 0; j < 8; j++) {
            float t  = v[j] * inv;
            float t1 = rintf(t);
            int c1 = (int)t1;
            int c2 = (int)rintf((t - t1) * 128.f);
            u1 |= ((unsigned long long)(unsigned char)(signed char)c1) << (8 * j);
            u2 |= ((unsigned long long)(unsigned char)(signed char)c2) << (8 * j);
        }
        size_t o = (size_t)row * H_DIM + lt * 8;
        *(unsigned long long*)(q1 + o) = u1;
        *(unsigned long long*)(q2 + o) = u2;
        return;
    }

    if (bid <= NB_CONV1 + NB_WD) {
        int grp = tid >> 6;
        int lt  = tid & 63;
        int row = (bid - 1 - NB_CONV1) * 8 + grp;
        bool active = row < NE * H_DIM;

        float v[8] = {0, 0, 0, 0, 0, 0, 0, 0};
        if (active) {
            const float4* p4 = (const float4*)(wd + (size_t)row * I_DIM + lt * 8);
            float4 a = p4[0], b = p4[1];
            v[0] = a.x; v[1] = a.y; v[2] = a.z; v[3] = a.w;
            v[4] = b.x; v[5] = b.y; v[6] = b.z; v[7] = b.w;
        }
        float m = 0.f;
#pragma unroll
        for (int j = 0; j < 8; j++) m = fmaxf(m, fabsf(v[j]));
#pragma unroll
        for (int o = 16; o; o >>= 1) m = fmaxf(m, __shfl_xor_sync(0xFFFFFFFFu, m, o));
        __shared__ float sm2[16];
        __shared__ float s_inv2[8];
        if ((lt & 31) == 0) sm2[grp * 2 + (lt >> 5)] = m;
        __syncthreads();
        if (lt == 0) {
            float mm = fmaxf(sm2[grp * 2], sm2[grp * 2 + 1]);
            if (active) g_swd[row] = mm * (1.f / 127.f);
            s_inv2[grp] = (mm > 0.f) ? (127.f / mm) : 0.f;
        }
        __syncthreads();
        if (!active) return;
        float inv = s_inv2[grp];
        unsigned long long u1 = 0, u2 = 0;
#pragma unroll
        for (int j = 0; j < 8; j++) {
            float t  = v[j] * inv;
            float t1 = rintf(t);
            int c1 = (int)t1;
            int c2 = (int)rintf((t - t1) * 128.f);
            u1 |= ((unsigned long long)(unsigned char)(signed char)c1) << (8 * j);
            u2 |= ((unsigned long long)(unsigned char)(signed char)c2) << (8 * j);
        }
        size_t o = (size_t)row * I_DIM + lt * 8;
        *(unsigned long long*)(g_wd1 + o) = u1;
        *(unsigned long long*)(g_wd2 + o) = u2;
        return;
    }

    // ---- zero the output buffer (pass2 accumulates into it with red.add) ----
    {
        int zb = bid - 1 - NB_CONV1 - NB_WD;           // 0..NB_OUT-1
        size_t i = ((size_t)zb * 512 + tid) * 4;
        if (i < (size_t)T_TOK * H_DIM)
            *(float4*)(out + i) = make_float4(0.f, 0.f, 0.f, 0.f);
    }
}

// ---------------- quant_h: rows of 512, 8 rows per block ----------------
__global__ void __launch_bounds__(512) quant_h_kernel() {
    int grp = threadIdx.x >> 6;
    int lt  = threadIdx.x & 63;
    int row = blockIdx.x * 8 + grp;
    bool active = row < NPAIR;

    float v[8] = {0, 0, 0, 0, 0, 0, 0, 0};
    if (active) {
        const float4* p4 = (const float4*)(g_h + (size_t)row * I_DIM + lt * 8);
        float4 a = p4[0], b = p4[1];
        v[0] = a.x; v[1] = a.y; v[2] = a.z; v[3] = a.w;
        v[4] = b.x; v[5] = b.y; v[6] = b.z; v[7] = b.w;
    }
    float m = 0.f;
#pragma unroll
    for (int j = 0; j < 8; j++) m = fmaxf(m, fabsf(v[j]));
#pragma unroll
    for (int o = 16; o; o >>= 1) m = fmaxf(m, __shfl_xor_sync(0xFFFFFFFFu, m, o));
    __shared__ float sm[16];
    __shared__ float s_inv[8];
    if ((lt & 31) == 0) sm[grp * 2 + (lt >> 5)] = m;
    __syncthreads();
    if (lt == 0) {
        float mm = fmaxf(sm[grp * 2], sm[grp * 2 + 1]);
        if (active) g_sh[row] = mm * (1.f / 127.f);
        s_inv[grp] = (mm > 0.f) ? (127.f / mm) : 0.f;
    }
    __syncthreads();
    if (!active) return;
    float inv = s_inv[grp];
    unsigned long long u1 = 0, u2 = 0;
#pragma unroll
    for (int j = 0; j < 8; j++) {
        float t  = v[j] * inv;
        float t1 = rintf(t);
        int c1 = (int)t1;
        int c2 = (int)rintf((t - t1) * 128.f);
        u1 |= ((unsigned long long)(unsigned char)(signed char)c1) << (8 * j);
        u2 |= ((unsigned long long)(unsigned char)(signed char)c2) << (8 * j);
    }
    size_t o = (size_t)row * I_DIM + lt * 8;
    *(unsigned long long*)(g_h1 + o) = u1;
    *(unsigned long long*)(g_h2 + o) = u2;
}

// ============================================================================
// pass1: grouped int8 IMMA GEMM, CTA 64x64, K=1024, fused up+gate,
// two-level int8 (3-term). Dual-sync 2-stage pipeline (proven).
// ============================================================================
#define P1_TILE  8192
#define P1_STAGE (6 * P1_TILE)                  // 48KB
#define P1_SMEM  (2048 + 2 * P1_STAGE)          // 100352 -> 2 CTAs/SM
#define P1_NC    8

__global__ void __launch_bounds__(256, 2) pass1_mma() {
    int e     = blockIdx.z;
    int mBase = g_offsets[e];
    int mEnd  = g_offsets[e + 1];
    int m0    = mBase + blockIdx.y * 64;
    if (m0 >= mEnd) return;
    int n0 = blockIdx.x * 64;

    extern __shared__ char smem[];
    int*   s_tok = (int*)smem;
    float* s_wt  = (float*)(smem + 256);
    float* s_sa  = (float*)(smem + 512);
    float* s_su  = (float*)(smem + 768);
    float* s_sg  = (float*)(smem + 1024);
    uint32_t tb  = smem_u32(smem + 2048);

    int tid = threadIdx.x, wid = tid >> 5, lane = tid & 31;
    for (int r = tid; r < 64; r += 256) {
        int gm = m0 + r;
        int slot = (gm < mEnd) ? g_slot[gm] : g_slot[mBase];
        int tok = slot >> 2;
        s_tok[r] = tok;
        s_wt[r]  = g_wt[slot];
        s_sa[r]  = g_sx[tok];
        s_su[r]  = g_su[e * I_DIM + n0 + r];
        s_sg[r]  = g_sg[e * I_DIM + n0 + r];
    }
    __syncthreads();

    int lrow = tid >> 2;
    int qp   = tid & 3;
    uint32_t rbase = (uint32_t)lrow * 128;
    uint32_t cswz  = (rbase >> 3) & 0x70;
    uint32_t d0 = rbase + (((uint32_t)(qp * 32)) ^ cswz);
    uint32_t d1 = rbase + (((uint32_t)(qp * 32 + 16)) ^ cswz);
    size_t aoff = (size_t)s_tok[lrow] * H_DIM + qp * 32;
    size_t boff = ((size_t)e * I_DIM + n0 + lrow) * H_DIM + qp * 32;
    const signed char* sA1 = g_x1 + aoff;
    const signed char* sA2 = g_x2 + aoff;
    const signed char* sU1 = g_u1 + boff;
    const signed char* sU2 = g_u2 + boff;
    const signed char* sG1 = g_g1 + boff;
    const signed char* sG2 = g_g2 + boff;

    int dU1[2][2][4], dU2[2][2][4], dG1[2][2][4], dG2[2][2][4];
#pragma unroll
    for (int a = 0; a < 2; a++)
#pragma unroll
        for (int b = 0; b < 2; b++)
#pragma unroll
            for (int c = 0; c < 4; c++) {
                dU1[a][b][c] = 0; dU2[a][b][c] = 0;
                dG1[a][b][c] = 0; dG2[a][b][c] = 0;
            }

    int wm = (wid >> 2) * 32;
    int wn = (wid & 3) * 16;
    int lgrp = lane >> 3, lr = lane & 7;
    int rowA = wm + (lgrp & 1) * 8 + lr;
    int rowB = wn + (lgrp >> 1) * 8 + lr;
    int colA = (lgrp >> 1) * 16;
    int colB = (lgrp & 1) * 16;

    {
        uint32_t sb_ = tb;
        cp_async16(sb_ + d0, sA1);                   cp_async16(sb_ + d1, sA1 + 16);
        cp_async16(sb_ + P1_TILE + d0, sA2);         cp_async16(sb_ + P1_TILE + d1, sA2 + 16);
        cp_async16(sb_ + 2 * P1_TILE + d0, sU1);     cp_async16(sb_ + 2 * P1_TILE + d1, sU1 + 16);
        cp_async16(sb_ + 3 * P1_TILE + d0, sU2);     cp_async16(sb_ + 3 * P1_TILE + d1, sU2 + 16);
        cp_async16(sb_ + 4 * P1_TILE + d0, sG1);     cp_async16(sb_ + 4 * P1_TILE + d1, sG1 + 16);
        cp_async16(sb_ + 5 * P1_TILE + d0, sG2);     cp_async16(sb_ + 5 * P1_TILE + d1, sG2 + 16);
        asm volatile("cp.async.commit_group;" ::: "memory");
    }

    for (int c = 0; c < P1_NC; c++) {
        if (c + 1 < P1_NC) {
            int k0 = (c + 1) * 128;
            uint32_t sb_ = tb + ((c + 1) & 1) * P1_STAGE;
            cp_async16(sb_ + d0, sA1 + k0);                cp_async16(sb_ + d1, sA1 + k0 + 16);
            cp_async16(sb_ + P1_TILE + d0, sA2 + k0);      cp_async16(sb_ + P1_TILE + d1, sA2 + k0 + 16);
            cp_async16(sb_ + 2 * P1_TILE + d0, sU1 + k0);  cp_async16(sb_ + 2 * P1_TILE + d1, sU1 + k0 + 16);
            cp_async16(sb_ + 3 * P1_TILE + d0, sU2 + k0);  cp_async16(sb_ + 3 * P1_TILE + d1, sU2 + k0 + 16);
            cp_async16(sb_ + 4 * P1_TILE + d0, sG1 + k0);  cp_async16(sb_ + 4 * P1_TILE + d1, sG1 + k0 + 16);
            cp_async16(sb_ + 5 * P1_TILE + d0, sG2 + k0);  cp_async16(sb_ + 5 * P1_TILE + d1, sG2 + k0 + 16);
            asm volatile("cp.async.commit_group;" ::: "memory");
            asm volatile("cp.async.wait_group 1;" ::: "memory");
        } else {
            asm volatile("cp.async.wait_group 0;" ::: "memory");
        }
        __syncthreads();

        uint32_t st = tb + (c & 1) * P1_STAGE;
        uint32_t aQ1 = st, aQ2 = st + P1_TILE;
        uint32_t bU1 = st + 2 * P1_TILE, bU2 = st + 3 * P1_TILE;
        uint32_t bG1 = st + 4 * P1_TILE, bG2 = st + 5 * P1_TILE;

#pragma unroll
        for (int s = 0; s < 4; s++) {
            int kaB = s * 32 + colA;
            int kbB = s * 32 + colB;
            uint32_t A1f[2][4], A2f[2][4];
            ldmx4(A1f[0], aQ1 + SWZ(rowA * 128 + kaB));
            ldmx4(A1f[1], aQ1 + SWZ((rowA + 16) * 128 + kaB));
            ldmx4(A2f[0], aQ2 + SWZ(rowA * 128 + kaB));
            ldmx4(A2f[1], aQ2 + SWZ((rowA + 16) * 128 + kaB));
            uint32_t U1f[4], U2f[4], G1f[4], G2f[4];
            {
                uint32_t off = SWZ(rowB * 128 + kbB);
                ldmx4(U1f, bU1 + off);
                ldmx4(U2f, bU2 + off);
                ldmx4(G1f, bG1 + off);
                ldmx4(G2f, bG2 + off);
            }
#pragma unroll
            for (int mi = 0; mi < 2; mi++)
#pragma unroll
                for (int nf = 0; nf < 2; nf++) {
                    imma16832(dU1[mi][nf], A1f[mi], U1f[nf * 2], U1f[nf * 2 + 1]);
                    imma16832(dG1[mi][nf], A1f[mi], G1f[nf * 2], G1f[nf * 2 + 1]);
                }
#pragma unroll
            for (int mi = 0; mi < 2; mi++)
#pragma unroll
                for (int nf = 0; nf < 2; nf++) {
                    imma16832(dU2[mi][nf], A1f[mi], U2f[nf * 2], U2f[nf * 2 + 1]);
                    imma16832(dG2[mi][nf], A1f[mi], G2f[nf * 2], G2f[nf * 2 + 1]);
                }
#pragma unroll
            for (int mi = 0; mi < 2; mi++)
#pragma unroll
                for (int nf = 0; nf < 2; nf++) {
                    imma16832(dU2[mi][nf], A2f[mi], U1f[nf * 2], U1f[nf * 2 + 1]);
                    imma16832(dG2[mi][nf], A2f[mi], G1f[nf * 2], G1f[nf * 2 + 1]);
                }
        }
        __syncthreads();
    }

    // ---- epilogue ----
    int r4 = lane >> 2, c2 = (lane & 3) * 2;
#pragma unroll
    for (int mi = 0; mi < 2; mi++) {
#pragma unroll
        for (int half = 0; half < 2; half++) {
            int row = wm + mi * 16 + half * 8 + r4;
            int gm  = m0 + row;
            if (gm >= mEnd) continue;
            float w  = s_wt[row];
            float sa = s_sa[row];
#pragma unroll
            for (int nf = 0; nf < 2; nf++) {
                int colloc = wn + nf * 8 + c2;
                int col = n0 + colloc;
                float su0 = sa * s_su[colloc], su1 = sa * s_su[colloc + 1];
                float sg0 = sa * s_sg[colloc], sg1 = sa * s_sg[colloc + 1];
                int idx = half * 2;
                float u0 = w * su0 * ((float)dU1[mi][nf][idx]     + 0.0078125f * (float)dU2[mi][nf][idx]);
                float u1 = w * su1 * ((float)dU1[mi][nf][idx + 1] + 0.0078125f * (float)dU2[mi][nf][idx + 1]);
                float gg0 = w * sg0 * ((float)dG1[mi][nf][idx]     + 0.0078125f * (float)dG2[mi][nf][idx]);
                float gg1 = w * sg1 * ((float)dG1[mi][nf][idx + 1] + 0.0078125f * (float)dG2[mi][nf][idx + 1]);
                float r0 = w * (gg0 / (1.f + __expf(-gg0))) * u0;
                float r1 = w * (gg1 / (1.f + __expf(-gg1))) * u1;
                *(float2*)&g_h[(size_t)gm * I_DIM + col] = make_float2(r0, r1);
            }
        }
    }
}

// ============================================================================
// pass2: grouped int8 IMMA GEMM h @ w_down^T, CTA 64x64, K=512, two-level int8.
// Epilogue accumulates directly into out with red.global.add.f32.
// ============================================================================
#define P2_TILE  8192
#define P2_STAGE (4 * P2_TILE)                  // 32KB
#define P2_SMEM  (2048 + 2 * P2_STAGE)          // 67584 -> 3 CTAs/SM
#define P2_NC    4

__global__ void __launch_bounds__(256, 3) pass2_mma(float* __restrict__ out) {
    int e     = blockIdx.z;
    int mBase = g_offsets[e];
    int mEnd  = g_offsets[e + 1];
    int m0    = mBase + blockIdx.y * 64;
    if (m0 >= mEnd) return;
    int n0 = blockIdx.x * 64;

    extern __shared__ char smem[];
    int*   s_slot = (int*)smem;            // 64
    float* s_sa   = (float*)(smem + 256);  // 64
    float* s_sb   = (float*)(smem + 512);  // 64
    int*   s_row  = (int*)(smem + 768);    // 64
    uint32_t tb = smem_u32(smem + 2048);

    int tid = threadIdx.x, wid = tid >> 5, lane = tid & 31;
    for (int r = tid; r < 64; r += 256) {
        int gm = m0 + r;
        int rr = (gm < mEnd) ? gm : mBase;
        s_row[r]  = rr;
        s_slot[r] = (gm < mEnd) ? g_slot[gm] : 0;
        s_sa[r]   = g_sh[rr];
        s_sb[r]   = g_swd[e * H_DIM + n0 + r];
    }
    __syncthreads();

    int lrow = tid >> 2;
    int qp   = tid & 3;
    uint32_t rbase = (uint32_t)lrow * 128;
    uint32_t cswz  = (rbase >> 3) & 0x70;
    uint32_t d0 = rbase + (((uint32_t)(qp * 32)) ^ cswz);
    uint32_t d1 = rbase + (((uint32_t)(qp * 32 + 16)) ^ cswz);
    size_t aoff = (size_t)s_row[lrow] * I_DIM + qp * 32;
    size_t boff = ((size_t)e * H_DIM + n0 + lrow) * I_DIM + qp * 32;
    const signed char* sA1 = g_h1 + aoff;
    const signed char* sA2 = g_h2 + aoff;
    const signed char* sB1 = g_wd1 + boff;
    const signed char* sB2 = g_wd2 + boff;

    int d1a[2][2][4], d2a[2][2][4];
#pragma unroll
    for (int a = 0; a < 2; a++)
#pragma unroll
        for (int b = 0; b < 2; b++)
#pragma unroll
            for (int c = 0; c < 4; c++) { d1a[a][b][c] = 0; d2a[a][b][c] = 0; }

    int wm = (wid >> 2) * 32;
    int wn = (wid & 3) * 16;
    int lgrp = lane >> 3, lr = lane & 7;
    int rowA = wm + (lgrp & 1) * 8 + lr;
    int rowB = wn + (lgrp >> 1) * 8 + lr;
    int colA = (lgrp >> 1) * 16;
    int colB = (lgrp & 1) * 16;

    {
        uint32_t sb_ = tb;
        cp_async16(sb_ + d0, sA1);                 cp_async16(sb_ + d1, sA1 + 16);
        cp_async16(sb_ + P2_TILE + d0, sA2);       cp_async16(sb_ + P2_TILE + d1, sA2 + 16);
        cp_async16(sb_ + 2 * P2_TILE + d0, sB1);   cp_async16(sb_ + 2 * P2_TILE + d1, sB1 + 16);
        cp_async16(sb_ + 3 * P2_TILE + d0, sB2);   cp_async16(sb_ + 3 * P2_TILE + d1, sB2 + 16);
        asm volatile("cp.async.commit_group;" ::: "memory");
    }

    for (int c = 0; c < P2_NC; c++) {
        if (c + 1 < P2_NC) {
            int k0 = (c + 1) * 128;
            uint32_t sb_ = tb + ((c + 1) & 1) * P2_STAGE;
            cp_async16(sb_ + d0, sA1 + k0);                 cp_async16(sb_ + d1, sA1 + k0 + 16);
            cp_async16(sb_ + P2_TILE + d0, sA2 + k0);       cp_async16(sb_ + P2_TILE + d1, sA2 + k0 + 16);
            cp_async16(sb_ + 2 * P2_TILE + d0, sB1 + k0);   cp_async16(sb_ + 2 * P2_TILE + d1, sB1 + k0 + 16);
            cp_async16(sb_ + 3 * P2_TILE + d0, sB2 + k0);   cp_async16(sb_ + 3 * P2_TILE + d1, sB2 + k0 + 16);
            asm volatile("cp.async.commit_group;" ::: "memory");
            asm volatile("cp.async.wait_group 1;" ::: "memory");
        } else {
            asm volatile("cp.async.wait_group 0;" ::: "memory");
        }
        __syncthreads();

        uint32_t st = tb + (c & 1) * P2_STAGE;
        uint32_t a1 = st, a2 = st + P2_TILE;
        uint32_t b1 = st + 2 * P2_TILE, b2 = st + 3 * P2_TILE;

#pragma unroll
        for (int s = 0; s < 4; s++) {
            int kaB = s * 32 + colA;
            int kbB = s * 32 + colB;
            uint32_t A1f[2][4], A2f[2][4];
            ldmx4(A1f[0], a1 + SWZ(rowA * 128 + kaB));
            ldmx4(A1f[1], a1 + SWZ((rowA + 16) * 128 + kaB));
            ldmx4(A2f[0], a2 + SWZ(rowA * 128 + kaB));
            ldmx4(A2f[1], a2 + SWZ((rowA + 16) * 128 + kaB));
            uint32_t B1f[4], B2f[4];
            {
                uint32_t off = SWZ(rowB * 128 + kbB);
                ldmx4(B1f, b1 + off);
                ldmx4(B2f, b2 + off);
            }
#pragma unroll
            for (int mi = 0; mi < 2; mi++)
#pragma unroll
                for (int nf = 0; nf < 2; nf++)
                    imma16832(d1a[mi][nf], A1f[mi], B1f[nf * 2], B1f[nf * 2 + 1]);
#pragma unroll
            for (int mi = 0; mi < 2; mi++)
#pragma unroll
                for (int nf = 0; nf < 2; nf++)
                    imma16832(d2a[mi][nf], A1f[mi], B2f[nf * 2], B2f[nf * 2 + 1]);
#pragma unroll
            for (int mi = 0; mi < 2; mi++)
#pragma unroll
                for (int nf = 0; nf < 2; nf++)
                    imma16832(d2a[mi][nf], A2f[mi], B1f[nf * 2], B1f[nf * 2 + 1]);
        }
        __syncthreads();
    }

    // ---- epilogue: dequant + fire-and-forget accumulate into out ----
    int r4 = lane >> 2, c2 = (lane & 3) * 2;
#pragma unroll
    for (int mi = 0; mi < 2; mi++) {
#pragma unroll
        for (int half = 0; half < 2; half++) {
            int row = wm + mi * 16 + half * 8 + r4;
            int gm  = m0 + row;
            if (gm >= mEnd) continue;
            int t = s_slot[row] >> 2;          // token
            float sa = s_sa[row];
            float* op = out + (size_t)t * H_DIM;
#pragma unroll
            for (int nf = 0; nf < 2; nf++) {
                int colloc = wn + nf * 8 + c2;
                int col = n0 + colloc;
                float sb0 = sa * s_sb[colloc];
                float sb1 = sa * s_sb[colloc + 1];
                int idx = half * 2;
                float v0 = sb0 * ((float)d1a[mi][nf][idx]     + 0.0078125f * (float)d2a[mi][nf][idx]);
                float v1 = sb1 * ((float)d1a[mi][nf][idx + 1] + 0.0078125f * (float)d2a[mi][nf][idx + 1]);
                red_add_f32(op + col, v0);
                red_add_f32(op + col + 1, v1);
            }
        }
    }
}

// ---------------- launch ----------------
extern "C" void kernel_launch(void* const* d_in, const int* in_sizes, int n_in,
                              void* d_out, int out_size)
{
    const float* x             = (const float*)d_in[0];
    const float* router_logits = (const float*)d_in[1];
    const float* w_up          = (const float*)d_in[2];
    const float* w_gate        = (const float*)d_in[3];
    const float* w_down        = (const float*)d_in[4];
    float* out = (float*)d_out;

    cudaFuncSetAttribute(pass1_mma, cudaFuncAttributeMaxDynamicSharedMemorySize, P1_SMEM);
    cudaFuncSetAttribute(pass2_mma, cudaFuncAttributeMaxDynamicSharedMemorySize, P2_SMEM);

    // #1 prep (routing + conversions + out zeroing), #2 pass1, #3 quant_h,
    // #4 pass2 (profiled; reduces into out via red.add)
    prep_kernel<<<NB_PREP, 512>>>(router_logits, x, w_up, w_gate, w_down, out);

    dim3 g1(I_DIM / 64, T_TOK / 64, NE);
    pass1_mma<<<g1, 256, P1_SMEM>>>();

    quant_h_kernel<<<(NPAIR + 7) / 8, 512>>>();

    dim3 g2(H_DIM / 64, T_TOK / 64, NE);
    pass2_mma<<<g2, 256, P2_SMEM>>>(out);
}